// round 2
// baseline (speedup 1.0000x reference)
#include <cuda_runtime.h>
#include <math.h>
#include <stdint.h>

// Problem constants
#define N_POS   65536          // B*H*W = 16*64*64
#define N_E     2048           // codebook entries
#define C_DIM   64             // embedding dim
#define PLANE   4096           // H*W
#define ZQ_ELEMS 4194304       // 16*64*64*64
#define TAU     0.08f          // ambiguity margin for tf32 pass

// Persistent device scratch (no allocations allowed)
__device__ int                g_idx[N_POS];
__device__ int                g_hist[N_E];
__device__ float              g_loss;
__device__ int                g_nflag;
__device__ int                g_flag[N_POS];
__device__ unsigned long long g_fb_key[N_POS];

// ---------------------------------------------------------------------------
// monotonic float->uint mapping (order-preserving for all finite floats)
// ---------------------------------------------------------------------------
__device__ __forceinline__ unsigned int ordered_u32(float f) {
    unsigned int u = __float_as_uint(f);
    return (u & 0x80000000u) ? ~u : (u | 0x80000000u);
}

__device__ __forceinline__ unsigned int f2tf32(float f) {
    unsigned int u;
    asm("cvt.rna.tf32.f32 %0, %1;" : "=r"(u) : "f"(f));
    return u;
}

// ---------------------------------------------------------------------------
// Kernel 0: clear accumulators (every launch; graph replay safe)
// ---------------------------------------------------------------------------
__global__ void vq_init_kernel() {
    int gt = blockIdx.x * 256 + threadIdx.x;           // grid = 256 blocks
    if (gt < N_POS) g_fb_key[gt] = 0ull;
    if (gt < N_E)   g_hist[gt]   = 0;
    if (gt == 0) { g_loss = 0.0f; g_nflag = 0; }
}

// ---------------------------------------------------------------------------
// Kernel 1: tf32 tensor-core argmax pass.
// Block = 128 positions x 2048 codes. 256 threads (8 warps); warp w owns a
// 16-position m16 stripe, loops all codes in n8 steps via mma.m16n8k8 tf32.
// Tracks top-2 values + top-1 index per position; flags gap < TAU.
// ---------------------------------------------------------------------------
extern __shared__ unsigned int tc_smem[];

__global__ void __launch_bounds__(256, 2)
vq_tc_kernel(const float* __restrict__ z, const float* __restrict__ cb) {
    unsigned int* z_s  = tc_smem;                 // [128 pos][stride 68] tf32 bits
    unsigned int* cb_s = tc_smem + 128 * 68;      // [64 k][stride 136] tf32 bits

    const int tid  = threadIdx.x;
    const int warp = tid >> 5;
    const int lane = tid & 31;
    const int g    = lane >> 2;    // group id 0..7
    const int tig  = lane & 3;     // thread-in-group 0..3

    const int n0 = blockIdx.x * 128;
    const int b  = n0 >> 12;
    const int p0 = n0 & 4095;
    const float* zb = z + (size_t)b * (C_DIM * PLANE) + p0;

    // ---- load z tile -> z_s[pos][c] (tf32-rounded), coalesced global reads ----
    #pragma unroll
    for (int kk = 0; kk < 8; kk++) {
        int fid = tid + kk * 256;                  // 2048 float4 units
        int c   = fid >> 5;                        // 0..63
        int pg  = fid & 31;                        // pos group of 4
        float4 v = *(const float4*)(zb + c * PLANE + pg * 4);
        z_s[(pg * 4 + 0) * 68 + c] = f2tf32(v.x);
        z_s[(pg * 4 + 1) * 68 + c] = f2tf32(v.y);
        z_s[(pg * 4 + 2) * 68 + c] = f2tf32(v.z);
        z_s[(pg * 4 + 3) * 68 + c] = f2tf32(v.w);
    }
    __syncthreads();

    // ---- A fragments for this warp's m16 stripe (held in regs all kernel) ----
    unsigned int a[8][4];
    {
        const int r0 = warp * 16 + g;
        const int r1 = r0 + 8;
        #pragma unroll
        for (int s = 0; s < 8; s++) {
            a[s][0] = z_s[r0 * 68 + 8 * s + tig];
            a[s][1] = z_s[r1 * 68 + 8 * s + tig];
            a[s][2] = z_s[r0 * 68 + 8 * s + tig + 4];
            a[s][3] = z_s[r1 * 68 + 8 * s + tig + 4];
        }
    }

    float v1[2] = { -1e30f, -1e30f };
    float v2[2] = { -1e30f, -1e30f };
    int   i1[2] = { 0, 0 };

    for (int chunk = 0; chunk < 16; chunk++) {
        __syncthreads();
        // ---- load 128-code chunk -> cb_s[k][code] (tf32), stride 136 ----
        #pragma unroll
        for (int kk = 0; kk < 8; kk++) {
            int fid  = tid + kk * 256;             // 2048 float4 units
            int code = fid & 127;
            int c4   = fid >> 7;                   // 0..15
            float4 v = *(const float4*)(cb + (size_t)(chunk * 128 + code) * C_DIM + c4 * 4);
            cb_s[(c4 * 4 + 0) * 136 + code] = f2tf32(v.x);
            cb_s[(c4 * 4 + 1) * 136 + code] = f2tf32(v.y);
            cb_s[(c4 * 4 + 2) * 136 + code] = f2tf32(v.z);
            cb_s[(c4 * 4 + 3) * 136 + code] = f2tf32(v.w);
        }
        __syncthreads();

        #pragma unroll
        for (int nn = 0; nn < 16; nn++) {
            float c0 = 0.f, c1 = 0.f, c2 = 0.f, c3 = 0.f;
            #pragma unroll
            for (int s = 0; s < 8; s++) {
                unsigned int b0 = cb_s[(8 * s + tig) * 136 + nn * 8 + g];
                unsigned int b1 = cb_s[(8 * s + tig + 4) * 136 + nn * 8 + g];
                asm volatile(
                    "mma.sync.aligned.m16n8k8.row.col.f32.tf32.tf32.f32 "
                    "{%0,%1,%2,%3}, {%4,%5,%6,%7}, {%8,%9}, {%0,%1,%2,%3};"
                    : "+f"(c0), "+f"(c1), "+f"(c2), "+f"(c3)
                    : "r"(a[s][0]), "r"(a[s][1]), "r"(a[s][2]), "r"(a[s][3]),
                      "r"(b0), "r"(b1));
            }
            const int col = chunk * 128 + nn * 8 + tig * 2;
            // running top-2 (strict > keeps first occurrence; cols ascend in-thread)
            if (c0 > v1[0]) { v2[0] = v1[0]; v1[0] = c0; i1[0] = col;     } else v2[0] = fmaxf(v2[0], c0);
            if (c1 > v1[0]) { v2[0] = v1[0]; v1[0] = c1; i1[0] = col + 1; } else v2[0] = fmaxf(v2[0], c1);
            if (c2 > v1[1]) { v2[1] = v1[1]; v1[1] = c2; i1[1] = col;     } else v2[1] = fmaxf(v2[1], c2);
            if (c3 > v1[1]) { v2[1] = v1[1]; v1[1] = c3; i1[1] = col + 1; } else v2[1] = fmaxf(v2[1], c3);
        }
    }

    // ---- merge top-2 across the 4 threads of each row group ----
    #pragma unroll
    for (int r = 0; r < 2; r++) {
        #pragma unroll
        for (int off = 1; off <= 2; off <<= 1) {
            float ov1 = __shfl_xor_sync(0xffffffffu, v1[r], off);
            int   oi1 = __shfl_xor_sync(0xffffffffu, i1[r], off);
            float ov2 = __shfl_xor_sync(0xffffffffu, v2[r], off);
            float nv2 = fmaxf(fmaxf(v2[r], ov2), fminf(v1[r], ov1));
            if (ov1 > v1[r] || (ov1 == v1[r] && oi1 < i1[r])) { v1[r] = ov1; i1[r] = oi1; }
            v2[r] = nv2;
        }
    }

    if (tig == 0) {
        #pragma unroll
        for (int r = 0; r < 2; r++) {
            int pos = n0 + warp * 16 + g + r * 8;
            g_idx[pos] = i1[r];
            if (v1[r] - v2[r] < TAU) {
                int slot = atomicAdd(&g_nflag, 1);
                g_flag[slot] = pos;
            }
        }
    }
}

// ---------------------------------------------------------------------------
// Kernel 2: exact fp32 rescue for flagged positions.
// grid = (8 code-chunks of 256, Y pos-groups of 16). Each thread: 1 position,
// 16 codes, full-precision fp32 dot (k ascending). Merge via u64 atomicMax
// key = ordered(val)<<32 | (2047-idx)  -> max = (best val, lowest idx).
// ---------------------------------------------------------------------------
#define FB_GRID_Y 128

__global__ void __launch_bounds__(256)
vq_fallback_kernel(const float* __restrict__ z, const float* __restrict__ cb) {
    __shared__ float z_fs[16][68];
    const int nf = g_nflag;
    const int t  = threadIdx.x;
    const int p  = t >> 4;          // 0..15 position slot
    const int l  = t & 15;          // 0..15 code lane

    for (int gidx = blockIdx.y; gidx * 16 < nf; gidx += FB_GRID_Y) {
        const int fi    = gidx * 16 + p;
        const bool valid = (fi < nf);
        const int pos   = valid ? g_flag[fi] : 0;
        const int b     = pos >> 12;
        const int pp    = pos & 4095;

        __syncthreads();
        // cooperative gathered z-row load: 16 lanes x 4 channels
        #pragma unroll
        for (int j = 0; j < 4; j++) {
            int c = l * 4 + j;
            z_fs[p][c] = z[(size_t)b * (C_DIM * PLANE) + (size_t)c * PLANE + pp];
        }
        __syncthreads();

        // cache this position's z row in registers
        float4 az[16];
        #pragma unroll
        for (int k4 = 0; k4 < 16; k4++) az[k4] = *(float4*)&z_fs[p][k4 * 4];

        float bv = -1e30f;
        int   bi = 0;
        const int cbase = blockIdx.x * 256 + l * 16;
        #pragma unroll 4
        for (int j = 0; j < 16; j++) {
            const int code = cbase + j;
            const float4* cr = (const float4*)(cb + (size_t)code * C_DIM);
            float acc = 0.0f;
            #pragma unroll
            for (int k4 = 0; k4 < 16; k4++) {
                float4 cv = cr[k4];
                acc = fmaf(az[k4].x, cv.x, acc);
                acc = fmaf(az[k4].y, cv.y, acc);
                acc = fmaf(az[k4].z, cv.z, acc);
                acc = fmaf(az[k4].w, cv.w, acc);
            }
            if (acc > bv) { bv = acc; bi = code; }
        }

        // merge across the 16 code lanes of this position (stays in 16-lane half)
        #pragma unroll
        for (int off = 1; off <= 8; off <<= 1) {
            float ov = __shfl_xor_sync(0xffffffffu, bv, off);
            int   oi = __shfl_xor_sync(0xffffffffu, bi, off);
            if (ov > bv || (ov == bv && oi < bi)) { bv = ov; bi = oi; }
        }
        if (l == 0 && valid) {
            unsigned long long key =
                ((unsigned long long)ordered_u32(bv) << 32) |
                (unsigned long long)(unsigned int)(2047 - bi);
            atomicMax(&g_fb_key[fi], key);
        }
    }
}

// ---------------------------------------------------------------------------
// Kernel 3: write rescued indices back
// ---------------------------------------------------------------------------
__global__ void vq_fixup_kernel() {
    const int nf = g_nflag;
    for (int i = blockIdx.x * 256 + threadIdx.x; i < nf; i += 32 * 256) {
        unsigned long long key = g_fb_key[i];
        g_idx[g_flag[i]] = 2047 - (int)(unsigned int)(key & 0xffffffffull);
    }
}

// ---------------------------------------------------------------------------
// Kernel 4: gather codebook[idx] -> z_q (transposed), loss sum, histogram,
// indices-as-float.
// ---------------------------------------------------------------------------
__global__ void __launch_bounds__(256)
vq_gather_kernel(const float* __restrict__ z, const float* __restrict__ cb,
                 float* __restrict__ out_zq, float* __restrict__ out_idx_f) {
    __shared__ int   sh_hist[N_E];
    __shared__ float sh_red[8];

    const int tid = threadIdx.x;
    #pragma unroll
    for (int k = tid; k < N_E; k += 256) sh_hist[k] = 0;
    __syncthreads();

    const int n = blockIdx.x * 256 + tid;
    const int e = g_idx[n];
    const int b = n >> 12;
    const int p = n & 4095;
    const float*  zb = z      + (size_t)b * (C_DIM * PLANE) + p;
    float*        ob = out_zq + (size_t)b * (C_DIM * PLANE) + p;
    const float4* cr = (const float4*)(cb + (size_t)e * C_DIM);

    float s = 0.0f;
    #pragma unroll
    for (int c4 = 0; c4 < 16; c4++) {
        float4 q = cr[c4];
        const float* zp0 = zb + (c4 * 4) * PLANE;
        float*       op0 = ob + (c4 * 4) * PLANE;
        float d;
        d = q.x - zp0[0];          s = fmaf(d, d, s); op0[0]          = q.x;
        d = q.y - zp0[PLANE];      s = fmaf(d, d, s); op0[PLANE]      = q.y;
        d = q.z - zp0[2 * PLANE];  s = fmaf(d, d, s); op0[2 * PLANE]  = q.z;
        d = q.w - zp0[3 * PLANE];  s = fmaf(d, d, s); op0[3 * PLANE]  = q.w;
    }

    out_idx_f[n] = (float)e;
    atomicAdd(&sh_hist[e], 1);

    #pragma unroll
    for (int off = 16; off; off >>= 1) s += __shfl_xor_sync(0xffffffffu, s, off);
    if ((tid & 31) == 0) sh_red[tid >> 5] = s;
    __syncthreads();
    if (tid == 0) {
        float t = 0.0f;
        #pragma unroll
        for (int w = 0; w < 8; w++) t += sh_red[w];
        atomicAdd(&g_loss, t);
    }

    #pragma unroll
    for (int k = tid; k < N_E; k += 256) {
        int v = sh_hist[k];
        if (v) atomicAdd(&g_hist[k], v);
    }
}

// ---------------------------------------------------------------------------
// Kernel 5: finalize loss scalar + perplexity
// ---------------------------------------------------------------------------
__global__ void vq_finalize_kernel(float* __restrict__ out) {
    __shared__ float red[256];
    const int tid = threadIdx.x;
    float part = 0.0f;
    #pragma unroll
    for (int k = tid; k < N_E; k += 256) {
        float em = (float)g_hist[k] * (1.0f / 65536.0f);
        part += em * logf(em + 1e-10f);
    }
    red[tid] = part;
    __syncthreads();
    for (int s = 128; s; s >>= 1) {
        if (tid < s) red[tid] += red[tid + s];
        __syncthreads();
    }
    if (tid == 0) {
        out[ZQ_ELEMS]     = g_loss * (1.25f / (float)ZQ_ELEMS);  // (BETA+1)*mean
        out[ZQ_ELEMS + 1] = expf(-red[0]);                       // perplexity
    }
}

// ---------------------------------------------------------------------------
// Launch chain (graph-capturable).
// Output layout: [ z_q (4194304) | loss (1) | perplexity (1) | indices (65536) ]
// ---------------------------------------------------------------------------
extern "C" void kernel_launch(void* const* d_in, const int* in_sizes, int n_in,
                              void* d_out, int out_size) {
    const float* z  = (const float*)d_in[0];
    const float* cb = (const float*)d_in[1];
    float* out = (float*)d_out;

    cudaFuncSetAttribute(vq_tc_kernel,
                         cudaFuncAttributeMaxDynamicSharedMemorySize, 70000);

    vq_init_kernel<<<256, 256>>>();
    vq_tc_kernel<<<N_POS / 128, 256, (128 * 68 + 64 * 136) * 4>>>(z, cb);
    vq_fallback_kernel<<<dim3(8, FB_GRID_Y), 256>>>(z, cb);
    vq_fixup_kernel<<<32, 256>>>();
    vq_gather_kernel<<<N_POS / 256, 256>>>(z, cb, out, out + ZQ_ELEMS + 2);
    vq_finalize_kernel<<<1, 256>>>(out);
    (void)in_sizes; (void)n_in; (void)out_size;
}